// round 4
// baseline (speedup 1.0000x reference)
#include <cuda_runtime.h>
#include <math.h>

// Problem constants (fixed shapes)
// B=4, N=4096, k=32, Cin=64, Cout=64, M=8
// P = B*N*k = 524288 points
// grouped_xyz: (4,3,4096,32), feature: (4,64,4096,32)
// weightbank: (64, 512) = [ci][m*64+c]
// out: (4,64,4096,32) fp32

#define NPTS 524288
#define NGROUPS 16384          // B*N
#define FEAT_CI_STRIDE 131072  // N*k
#define XYZ_B_STRIDE 393216    // 3*N*k

typedef unsigned long long ull;

__device__ float g_sum1[16], g_ss1[16];
__device__ float g_bn1_scale[16], g_bn1_bias[16];
__device__ float g_osum[64], g_oss[64];
__device__ float g_obn_scale[64], g_obn_bias[64];

__device__ __forceinline__ ull pack2(float a, float b) {
    ull r; asm("mov.b64 %0, {%1,%2};" : "=l"(r) : "f"(a), "f"(b)); return r;
}
__device__ __forceinline__ void fma2(ull& acc, ull a, ull b) {
    asm("fma.rn.f32x2 %0, %1, %2, %0;" : "+l"(acc) : "l"(a), "l"(b));
}
__device__ __forceinline__ float2 unpack2(ull v) {
    float2 r; asm("mov.b64 {%0,%1}, %2;" : "=f"(r.x), "=f"(r.y) : "l"(v)); return r;
}

// ---------------- K0: zero global stat accumulators ----------------
__global__ void k0_zero() {
    int i = threadIdx.x;
    if (i < 16) { g_sum1[i] = 0.f; g_ss1[i] = 0.f; }
    if (i < 64) { g_osum[i] = 0.f; g_oss[i] = 0.f; }
}

// ---------------- K1: ScoreNet conv1 BN stats ----------------
// 128 blocks x 512 threads, 8 points per thread
__global__ void k1_stats(const float* __restrict__ gxyz, const float* __restrict__ w1) {
    __shared__ float sw1[64];
    if (threadIdx.x < 64) sw1[threadIdx.x] = w1[threadIdx.x];
    __syncthreads();

    float s[16], q[16];
#pragma unroll
    for (int o = 0; o < 16; ++o) { s[o] = 0.f; q[o] = 0.f; }

    int gtid = blockIdx.x * 512 + threadIdx.x;
#pragma unroll
    for (int i = 0; i < 8; ++i) {
        int p = gtid + i * 65536;
        int b = p >> 17;                 // / (N*k)
        int rem = p & 131071;
        const float* gp = gxyz + (size_t)b * XYZ_B_STRIDE + rem;
        float x = gp[0], y = gp[FEAT_CI_STRIDE], z = gp[2 * FEAT_CI_STRIDE];
        float ed = sqrtf(x * x + y * y + z * z);
#pragma unroll
        for (int o = 0; o < 16; ++o) {
            float v = sw1[o * 4] * x + sw1[o * 4 + 1] * y + sw1[o * 4 + 2] * z + sw1[o * 4 + 3] * ed;
            s[o] += v; q[o] += v * v;
        }
    }
    // warp reduce
#pragma unroll
    for (int o = 0; o < 16; ++o) {
#pragma unroll
        for (int off = 16; off; off >>= 1) {
            s[o] += __shfl_xor_sync(0xFFFFFFFFu, s[o], off);
            q[o] += __shfl_xor_sync(0xFFFFFFFFu, q[o], off);
        }
    }
    if ((threadIdx.x & 31) == 0) {
#pragma unroll
        for (int o = 0; o < 16; ++o) {
            atomicAdd(&g_sum1[o], s[o]);
            atomicAdd(&g_ss1[o], q[o]);
        }
    }
}

// ---------------- K1b: fold BN1 into scale/bias ----------------
__global__ void k1b_fold(const float* __restrict__ g1, const float* __restrict__ b1) {
    int i = threadIdx.x;
    if (i < 16) {
        const float P = (float)NPTS;
        float mean = g_sum1[i] / P;
        float var = g_ss1[i] / P - mean * mean;
        float istd = rsqrtf(var + 1e-5f);
        float sc = istd * g1[i];
        g_bn1_scale[i] = sc;
        g_bn1_bias[i] = b1[i] - mean * sc;
    }
}

// ---------------- K2: fused main kernel ----------------
// 2048 blocks x 512 threads. Each block handles 8 (b,n) groups = 256 points.
// SMEM: W transposed [m][ci][c] (128KB) + scores (8KB) + params (1KB) + stat buf.
__global__ __launch_bounds__(512, 1)
void k2_main(const float* __restrict__ gxyz, const float* __restrict__ feat,
             const float* __restrict__ w1, const float* __restrict__ w2,
             const float* __restrict__ b2, const float* __restrict__ wbank,
             float* __restrict__ outp) {
    extern __shared__ float sm[];
    float* sW    = sm;              // 32768
    float* sS    = sm + 32768;      // 2048 (256 points x 8)
    float* sPar  = sm + 34816;      // 256
    float* sOsum = sm + 35072;      // 64
    float* sOss  = sm + 35136;      // 64

    const int tid = threadIdx.x;

    // params into SMEM
    if (tid < 64)        sPar[tid] = w1[tid];
    else if (tid < 192)  sPar[tid] = w2[tid - 64];
    else if (tid < 200)  sPar[tid] = b2[tid - 192];
    else if (tid < 216)  sPar[tid] = g_bn1_scale[tid - 200];
    else if (tid < 232)  sPar[tid] = g_bn1_bias[tid - 216];
    if (tid < 64) { sOsum[tid] = 0.f; sOss[tid] = 0.f; }

    // load weightbank transposed: sW[(m*64+ci)*64 + c] = wbank[ci*512 + m*64 + c]
    for (int idx = tid; idx < 32768; idx += 512) {
        int ci = idx >> 9;
        int m  = (idx >> 6) & 7;
        int c  = idx & 63;
        sW[(((m << 6) + ci) << 6) + c] = wbank[idx];
    }
    __syncthreads();   // params ready (sW not yet needed)

    // scores: threads 0..255 compute one point each
    if (tid < 256) {
        int p = tid, g = p >> 5, kk = p & 31;
        int gg = blockIdx.x * 8 + g;
        int b = gg >> 12, n = gg & 4095;
        const float* gp = gxyz + (size_t)b * XYZ_B_STRIDE + n * 32 + kk;
        float x = gp[0], y = gp[FEAT_CI_STRIDE], z = gp[2 * FEAT_CI_STRIDE];
        float ed = sqrtf(x * x + y * y + z * z);
        float h[16];
#pragma unroll
        for (int o = 0; o < 16; ++o) {
            float v = sPar[o * 4] * x + sPar[o * 4 + 1] * y + sPar[o * 4 + 2] * z + sPar[o * 4 + 3] * ed;
            h[o] = fmaxf(fmaf(v, sPar[200 + o], sPar[216 + o]), 0.f);
        }
        float sv[8];
        float mx = -1e30f;
#pragma unroll
        for (int j = 0; j < 8; ++j) {
            float a = sPar[192 + j];
#pragma unroll
            for (int o = 0; o < 16; ++o) a = fmaf(sPar[64 + j * 16 + o], h[o], a);
            sv[j] = a;
            mx = fmaxf(mx, a);
        }
        float den = 1.f;
#pragma unroll
        for (int j = 0; j < 8; ++j) { sv[j] = expf(sv[j] - mx); den += sv[j]; }
        float rden = 1.f / den;
#pragma unroll
        for (int j = 0; j < 8; ++j) sS[p * 8 + j] = sv[j] * rden;
    }
    __syncthreads();   // sW + sS ready

    // main contraction: thread = (channel c, point-slot ps). 8 points/thread/iter.
    const int c = tid & 63;
    const int ps = tid >> 6;      // 0..7
    float asum = 0.f, ass = 0.f;

    for (int it = 0; it < 4; ++it) {
        int g = it * 2 + (ps >> 2);
        int kk0 = (ps & 3) * 8;
        int gg = blockIdx.x * 8 + g;
        int b = gg >> 12, n = gg & 4095;
        const float* fp = feat + ((size_t)b << 23) + n * 32 + kk0;

        ull pm[8][4];
#pragma unroll
        for (int m = 0; m < 8; ++m)
#pragma unroll
            for (int j = 0; j < 4; ++j) pm[m][j] = 0ull;

#pragma unroll 2
        for (int ci = 0; ci < 64; ++ci) {
            float4 fa = *(const float4*)fp;
            float4 fb = *(const float4*)(fp + 4);
            fp += FEAT_CI_STRIDE;
            ull f0 = pack2(fa.x, fa.y), f1 = pack2(fa.z, fa.w);
            ull f2 = pack2(fb.x, fb.y), f3 = pack2(fb.z, fb.w);
            const float* wp = sW + (ci << 6) + c;
#pragma unroll
            for (int m = 0; m < 8; ++m) {
                float w = wp[m << 12];
                ull ww = pack2(w, w);
                fma2(pm[m][0], ww, f0);
                fma2(pm[m][1], ww, f1);
                fma2(pm[m][2], ww, f2);
                fma2(pm[m][3], ww, f3);
            }
        }

        // combine with scores + store pre-BN output
        int pbase = g * 32 + kk0;
        float* ob = outp + (((size_t)b * 64 + c) * 4096 + n) * 32 + kk0;
#pragma unroll
        for (int pr = 0; pr < 4; ++pr) {
            float2 pv[8];
#pragma unroll
            for (int m = 0; m < 8; ++m) pv[m] = unpack2(pm[m][pr]);
            const float* s0 = sS + (pbase + pr * 2) * 8;
            float o0 = 0.f, o1 = 0.f;
#pragma unroll
            for (int m = 0; m < 8; ++m) {
                o0 = fmaf(s0[m],     pv[m].x, o0);
                o1 = fmaf(s0[8 + m], pv[m].y, o1);
            }
            ob[pr * 2]     = o0;
            ob[pr * 2 + 1] = o1;
            asum += o0 + o1;
            ass  += o0 * o0 + o1 * o1;
        }
    }

    // out-BN stats reduction
    atomicAdd(&sOsum[c], asum);
    atomicAdd(&sOss[c], ass);
    __syncthreads();
    if (tid < 64) {
        atomicAdd(&g_osum[tid], sOsum[tid]);
        atomicAdd(&g_oss[tid],  sOss[tid]);
    }
}

// ---------------- K2b: fold output BN ----------------
__global__ void k2b_fold(const float* __restrict__ gout, const float* __restrict__ bout) {
    int i = threadIdx.x;
    if (i < 64) {
        const float P = (float)NPTS;
        float mean = g_osum[i] / P;
        float var = g_oss[i] / P - mean * mean;
        float istd = rsqrtf(var + 1e-5f);
        float sc = istd * gout[i];
        g_obn_scale[i] = sc;
        g_obn_bias[i] = bout[i] - mean * sc;
    }
}

// ---------------- K3: apply BN + ReLU in place ----------------
__global__ void k3_bnrelu(float* __restrict__ outp) {
    const int total4 = 8388608;   // 33554432 / 4
    int stride = gridDim.x * blockDim.x;
    for (int idx = blockIdx.x * blockDim.x + threadIdx.x; idx < total4; idx += stride) {
        int cch = (idx >> 15) & 63;
        float sc = g_obn_scale[cch], bi = g_obn_bias[cch];
        float4 v = ((const float4*)outp)[idx];
        v.x = fmaxf(fmaf(v.x, sc, bi), 0.f);
        v.y = fmaxf(fmaf(v.y, sc, bi), 0.f);
        v.z = fmaxf(fmaf(v.z, sc, bi), 0.f);
        v.w = fmaxf(fmaf(v.w, sc, bi), 0.f);
        ((float4*)outp)[idx] = v;
    }
}

extern "C" void kernel_launch(void* const* d_in, const int* in_sizes, int n_in,
                              void* d_out, int out_size) {
    const float* gxyz  = (const float*)d_in[0];
    const float* feat  = (const float*)d_in[1];
    const float* w1    = (const float*)d_in[2];
    const float* g1    = (const float*)d_in[3];
    const float* b1    = (const float*)d_in[4];
    const float* w2    = (const float*)d_in[5];
    const float* b2    = (const float*)d_in[6];
    const float* wbank = (const float*)d_in[7];
    const float* gout  = (const float*)d_in[8];
    const float* bout  = (const float*)d_in[9];
    float* outp = (float*)d_out;

    const size_t smem = 35200 * sizeof(float);   // 140800 B
    cudaFuncSetAttribute(k2_main, cudaFuncAttributeMaxDynamicSharedMemorySize, (int)smem);

    k0_zero<<<1, 64>>>();
    k1_stats<<<128, 512>>>(gxyz, w1);
    k1b_fold<<<1, 16>>>(g1, b1);
    k2_main<<<2048, 512, smem>>>(gxyz, feat, w1, w2, b2, wbank, outp);
    k2b_fold<<<1, 64>>>(gout, bout);
    k3_bnrelu<<<2048, 512>>>(outp);
}

// round 11
// speedup vs baseline: 2.6863x; 2.6863x over previous
#include <cuda_runtime.h>
#include <cuda_bf16.h>
#include <mma.h>
#include <math.h>
#include <cstdint>

// B=4, N=4096, k=32, Cin=64, Cout=64, M=8 ; P = 524288 points
// Stage 1 (WMMA bf16 hi/lo x3): proj[p][m*64+c] = sum_ci f[p][ci] * W[ci][m*64+c]
// Stage 2 (fp32): out[p][c] = sum_m s[p][m] * proj[p][m*64+c]

#define NPTS 524288
#define FEAT_CI_STRIDE 131072
#define XYZ_B_STRIDE 393216

using namespace nvcuda;

__device__ float g_sum1[16], g_ss1[16];
__device__ float g_bn1_scale[16], g_bn1_bias[16];
__device__ float g_osum[64], g_oss[64];
__device__ float g_obn_scale[64], g_obn_bias[64];

// weightbank split into bf16 hi/lo, same [ci][512] layout
__device__ __nv_bfloat16 g_Bh[32768];
__device__ __nv_bfloat16 g_Bl[32768];

__device__ __forceinline__ uint32_t cvt_bf16x2_pack(float hi_val, float lo_val) {
    uint32_t r; asm("cvt.rn.bf16x2.f32 %0, %1, %2;" : "=r"(r) : "f"(hi_val), "f"(lo_val)); return r;
}

// ---------------- K0: zero stat accumulators ----------------
__global__ void k0_zero() {
    int i = threadIdx.x;
    if (i < 16) { g_sum1[i] = 0.f; g_ss1[i] = 0.f; }
    if (i < 64) { g_osum[i] = 0.f; g_oss[i] = 0.f; }
}

// ---------------- KP: split weightbank into bf16 hi/lo ----------------
__global__ void kp_splitW(const float* __restrict__ wbank) {
    int idx = blockIdx.x * 512 + threadIdx.x;   // 0..32767
    float w = wbank[idx];
    __nv_bfloat16 hb = __float2bfloat16(w);
    g_Bh[idx] = hb;
    g_Bl[idx] = __float2bfloat16(w - __bfloat162float(hb));
}

// ---------------- K1: ScoreNet conv1 BN stats ----------------
__global__ void k1_stats(const float* __restrict__ gxyz, const float* __restrict__ w1) {
    __shared__ float sw1[64];
    if (threadIdx.x < 64) sw1[threadIdx.x] = w1[threadIdx.x];
    __syncthreads();
    float s[16], q[16];
#pragma unroll
    for (int o = 0; o < 16; ++o) { s[o] = 0.f; q[o] = 0.f; }
    int gtid = blockIdx.x * 512 + threadIdx.x;
#pragma unroll
    for (int i = 0; i < 8; ++i) {
        int p = gtid + i * 65536;
        int b = p >> 17;
        int rem = p & 131071;
        const float* gp = gxyz + (size_t)b * XYZ_B_STRIDE + rem;
        float x = gp[0], y = gp[FEAT_CI_STRIDE], z = gp[2 * FEAT_CI_STRIDE];
        float ed = sqrtf(x * x + y * y + z * z);
#pragma unroll
        for (int o = 0; o < 16; ++o) {
            float v = sw1[o * 4] * x + sw1[o * 4 + 1] * y + sw1[o * 4 + 2] * z + sw1[o * 4 + 3] * ed;
            s[o] += v; q[o] += v * v;
        }
    }
#pragma unroll
    for (int o = 0; o < 16; ++o) {
#pragma unroll
        for (int off = 16; off; off >>= 1) {
            s[o] += __shfl_xor_sync(0xFFFFFFFFu, s[o], off);
            q[o] += __shfl_xor_sync(0xFFFFFFFFu, q[o], off);
        }
    }
    if ((threadIdx.x & 31) == 0) {
#pragma unroll
        for (int o = 0; o < 16; ++o) { atomicAdd(&g_sum1[o], s[o]); atomicAdd(&g_ss1[o], q[o]); }
    }
}

__global__ void k1b_fold(const float* __restrict__ g1, const float* __restrict__ b1) {
    int i = threadIdx.x;
    if (i < 16) {
        const float P = (float)NPTS;
        float mean = g_sum1[i] / P;
        float var = g_ss1[i] / P - mean * mean;
        float sc = rsqrtf(var + 1e-5f) * g1[i];
        g_bn1_scale[i] = sc;
        g_bn1_bias[i] = b1[i] - mean * sc;
    }
}

// ---------------- K2: WMMA main kernel ----------------
// SMEM layout (bytes):
//   A^T hi [64ci][136p] bf16 : 17408   @ 0
//   A^T lo                  : 17408   @ 17408
//   B  hi  [64ci][88n] bf16 : 11264   @ 34816
//   B  lo                   : 11264   @ 46080
//   proj   [128p][72] f32   : 36864   @ 57344   (reused as [128][65] transpose buf)
//   scores [128p][8m] f32   :  4096   @ 94208
//   stats  128 f32          :   512   @ 98304
#define LDA 136
#define LDB 88
#define LDP 72
#define OFF_AH 0
#define OFF_AL 17408
#define OFF_BH 34816
#define OFF_BL 46080
#define OFF_P  57344
#define OFF_S  94208
#define OFF_STAT 98304
#define SMEM_SZ 98816

__global__ __launch_bounds__(256, 2)
void k2_wmma(const float* __restrict__ gxyz, const float* __restrict__ feat,
             const float* __restrict__ w1, const float* __restrict__ w2,
             const float* __restrict__ b2, float* __restrict__ outp) {
    extern __shared__ char smem[];
    __nv_bfloat16* sAh = (__nv_bfloat16*)(smem + OFF_AH);
    __nv_bfloat16* sAl = (__nv_bfloat16*)(smem + OFF_AL);
    __nv_bfloat16* sBh = (__nv_bfloat16*)(smem + OFF_BH);
    __nv_bfloat16* sBl = (__nv_bfloat16*)(smem + OFF_BL);
    float* sP = (float*)(smem + OFF_P);
    float* sS = (float*)(smem + OFF_S);
    float* sSum = (float*)(smem + OFF_STAT);
    float* sSS  = sSum + 64;

    const int tid = threadIdx.x;
    const int wid = tid >> 5;
    const int lane = tid & 31;
    const int gg0 = blockIdx.x * 4;
    const int b = gg0 >> 12;
    const int n0 = gg0 & 4095;

    if (tid < 64) { sSum[tid] = 0.f; sSS[tid] = 0.f; }

    // ---- form A^T hi/lo directly from global feature ----
    const float* fb = feat + ((size_t)b << 23) + n0 * 32;
    for (int idx = tid; idx < 2048; idx += 256) {
        int ci = idx >> 5, p4 = idx & 31;
        float4 v = ((const float4*)(fb + (size_t)ci * FEAT_CI_STRIDE))[p4];
        uint32_t h0 = cvt_bf16x2_pack(v.y, v.x);
        uint32_t h1 = cvt_bf16x2_pack(v.w, v.z);
        float2 f0 = __bfloat1622float2(*(__nv_bfloat162*)&h0);
        float2 f1 = __bfloat1622float2(*(__nv_bfloat162*)&h1);
        uint32_t l0 = cvt_bf16x2_pack(v.y - f0.y, v.x - f0.x);
        uint32_t l1 = cvt_bf16x2_pack(v.w - f1.y, v.z - f1.x);
        uint2 hv = make_uint2(h0, h1), lv = make_uint2(l0, l1);
        *(uint2*)((char*)sAh + ci * (LDA * 2) + p4 * 8) = hv;
        *(uint2*)((char*)sAl + ci * (LDA * 2) + p4 * 8) = lv;
    }

    // ---- scores for 128 points ----
    if (tid < 128) {
        int g = tid >> 5, kk = tid & 31;
        int n = n0 + g;
        const float* gp = gxyz + (size_t)b * XYZ_B_STRIDE + n * 32 + kk;
        float x = gp[0], y = gp[FEAT_CI_STRIDE], z = gp[2 * FEAT_CI_STRIDE];
        float ed = sqrtf(x * x + y * y + z * z);
        float h[16];
#pragma unroll
        for (int o = 0; o < 16; ++o) {
            float v = w1[o * 4] * x + w1[o * 4 + 1] * y + w1[o * 4 + 2] * z + w1[o * 4 + 3] * ed;
            h[o] = fmaxf(fmaf(v, g_bn1_scale[o], g_bn1_bias[o]), 0.f);
        }
        float sv[8], mx = -1e30f;
#pragma unroll
        for (int j = 0; j < 8; ++j) {
            float a = b2[j];
#pragma unroll
            for (int o = 0; o < 16; ++o) a = fmaf(w2[j * 16 + o], h[o], a);
            sv[j] = a; mx = fmaxf(mx, a);
        }
        float den = 1.f;
#pragma unroll
        for (int j = 0; j < 8; ++j) { sv[j] = expf(sv[j] - mx); den += sv[j]; }
        float rden = 1.f / den;
#pragma unroll
        for (int j = 0; j < 8; ++j) sS[tid * 8 + j] = sv[j] * rden;
    }

    // out accumulators: thread = (c = tid&63, ps = tid>>6), p = ps*32 + i
    const int c = tid & 63;
    const int ps = tid >> 6;
    float oacc[32];
#pragma unroll
    for (int i = 0; i < 32; ++i) oacc[i] = 0.f;

    const int wp = (wid & 3) * 32;   // p base of this warp's 32x32 out subtile
    const int wn = (wid >> 2) * 32;  // n base (within 64-wide m-chunk)

    for (int m = 0; m < 8; ++m) {
        // copy B chunk hi/lo: rows ci 0..63, cols m*64..m*64+63
        for (int i = tid; i < 512; i += 256) {
            int row = i >> 3, seg = i & 7;
            size_t srco = (size_t)row * 1024 + m * 128 + seg * 16;   // bytes
            uint4 vh = *(const uint4*)((const char*)g_Bh + srco);
            uint4 vl = *(const uint4*)((const char*)g_Bl + srco);
            *(uint4*)((char*)sBh + row * (LDB * 2) + seg * 16) = vh;
            *(uint4*)((char*)sBl + row * (LDB * 2) + seg * 16) = vl;
        }
        __syncthreads();   // B ready; also orders prev-iter combine before proj store

        wmma::fragment<wmma::accumulator, 16, 16, 16, float> acc[2][2];
#pragma unroll
        for (int i = 0; i < 2; ++i)
#pragma unroll
            for (int j = 0; j < 2; ++j) wmma::fill_fragment(acc[i][j], 0.f);

#pragma unroll
        for (int k = 0; k < 4; ++k) {
            const int ci0 = k * 16;
            wmma::fragment<wmma::matrix_a, 16, 16, 16, __nv_bfloat16, wmma::col_major> ah[2], al[2];
            wmma::fragment<wmma::matrix_b, 16, 16, 16, __nv_bfloat16, wmma::row_major> bh[2], bl[2];
#pragma unroll
            for (int i = 0; i < 2; ++i) {
                wmma::load_matrix_sync(ah[i], sAh + ci0 * LDA + wp + 16 * i, LDA);
                wmma::load_matrix_sync(al[i], sAl + ci0 * LDA + wp + 16 * i, LDA);
            }
#pragma unroll
            for (int j = 0; j < 2; ++j) {
                wmma::load_matrix_sync(bh[j], sBh + ci0 * LDB + wn + 16 * j, LDB);
                wmma::load_matrix_sync(bl[j], sBl + ci0 * LDB + wn + 16 * j, LDB);
            }
#pragma unroll
            for (int i = 0; i < 2; ++i)
#pragma unroll
                for (int j = 0; j < 2; ++j) {
                    wmma::mma_sync(acc[i][j], ah[i], bh[j], acc[i][j]);
                    wmma::mma_sync(acc[i][j], ah[i], bl[j], acc[i][j]);
                    wmma::mma_sync(acc[i][j], al[i], bh[j], acc[i][j]);
                }
        }
#pragma unroll
        for (int i = 0; i < 2; ++i)
#pragma unroll
            for (int j = 0; j < 2; ++j)
                wmma::store_matrix_sync(sP + (wp + 16 * i) * LDP + wn + 16 * j,
                                        acc[i][j], LDP, wmma::mem_row_major);
        __syncthreads();   // proj ready

        // combine: out[p][c] += s[p][m] * proj[p][c]
#pragma unroll 8
        for (int i = 0; i < 32; ++i) {
            int p = ps * 32 + i;
            oacc[i] = fmaf(sS[p * 8 + m], sP[p * LDP + c], oacc[i]);
        }
        // no sync: next iter's B copy is disjoint; next proj store is after its sync
    }
    __syncthreads();   // all combines done before reusing sP as transpose buffer

    // BN stats
    float su = 0.f, sq = 0.f;
#pragma unroll
    for (int i = 0; i < 32; ++i) { su += oacc[i]; sq += oacc[i] * oacc[i]; }
    atomicAdd(&sSum[c], su);
    atomicAdd(&sSS[c], sq);

    // transpose via smem [128][65], then coalesced float4 stores
    float* tb = sP;
#pragma unroll
    for (int i = 0; i < 32; ++i) tb[(ps * 32 + i) * 65 + c] = oacc[i];
    __syncthreads();
#pragma unroll
    for (int i = 0; i < 8; ++i) {
        int cc = wid * 8 + i;
        float4 v;
        v.x = tb[(lane * 4 + 0) * 65 + cc];
        v.y = tb[(lane * 4 + 1) * 65 + cc];
        v.z = tb[(lane * 4 + 2) * 65 + cc];
        v.w = tb[(lane * 4 + 3) * 65 + cc];
        ((float4*)(outp + ((size_t)b * 64 + cc) * 131072 + n0 * 32))[lane] = v;
    }
    if (tid < 64) { atomicAdd(&g_osum[tid], sSum[tid]); atomicAdd(&g_oss[tid], sSS[tid]); }
}

// ---------------- K2b: fold output BN ----------------
__global__ void k2b_fold(const float* __restrict__ gout, const float* __restrict__ bout) {
    int i = threadIdx.x;
    if (i < 64) {
        const float P = (float)NPTS;
        float mean = g_osum[i] / P;
        float var = g_oss[i] / P - mean * mean;
        float sc = rsqrtf(var + 1e-5f) * gout[i];
        g_obn_scale[i] = sc;
        g_obn_bias[i] = bout[i] - mean * sc;
    }
}

// ---------------- K3: apply BN + ReLU in place ----------------
__global__ void k3_bnrelu(float* __restrict__ outp) {
    const int total4 = 8388608;
    int stride = gridDim.x * blockDim.x;
    for (int idx = blockIdx.x * blockDim.x + threadIdx.x; idx < total4; idx += stride) {
        int cch = (idx >> 15) & 63;
        float sc = g_obn_scale[cch], bi = g_obn_bias[cch];
        float4 v = ((const float4*)outp)[idx];
        v.x = fmaxf(fmaf(v.x, sc, bi), 0.f);
        v.y = fmaxf(fmaf(v.y, sc, bi), 0.f);
        v.z = fmaxf(fmaf(v.z, sc, bi), 0.f);
        v.w = fmaxf(fmaf(v.w, sc, bi), 0.f);
        ((float4*)outp)[idx] = v;
    }
}

extern "C" void kernel_launch(void* const* d_in, const int* in_sizes, int n_in,
                              void* d_out, int out_size) {
    const float* gxyz  = (const float*)d_in[0];
    const float* feat  = (const float*)d_in[1];
    const float* w1    = (const float*)d_in[2];
    const float* g1    = (const float*)d_in[3];
    const float* b1    = (const float*)d_in[4];
    const float* w2    = (const float*)d_in[5];
    const float* b2    = (const float*)d_in[6];
    const float* wbank = (const float*)d_in[7];
    const float* gout  = (const float*)d_in[8];
    const float* bout  = (const float*)d_in[9];
    float* outp = (float*)d_out;

    cudaFuncSetAttribute(k2_wmma, cudaFuncAttributeMaxDynamicSharedMemorySize, SMEM_SZ);

    k0_zero<<<1, 64>>>();
    kp_splitW<<<64, 512>>>(wbank);
    k1_stats<<<128, 512>>>(gxyz, w1);
    k1b_fold<<<1, 16>>>(g1, b1);
    k2_wmma<<<4096, 256, SMEM_SZ>>>(gxyz, feat, w1, w2, b2, outp);
    k2b_fold<<<1, 64>>>(gout, bout);
    k3_bnrelu<<<2048, 512>>>(outp);
}

// round 13
// speedup vs baseline: 4.6900x; 1.7459x over previous
#include <cuda_runtime.h>
#include <cuda_bf16.h>
#include <math.h>
#include <cstdint>

// B=4, N=4096, k=32, Cin=64, Cout=64, M=8 ; P = 524288 points
// Stage 1 (mma.sync bf16 hi/lo x3): proj_m[p][c] = sum_ci f[p][ci] * W[ci][m*64+c]
// Stage 2 (in-register): out[p][c] = sum_m s[p][m] * proj_m[p][c]

#define NPTS 524288
#define FEAT_CI_STRIDE 131072
#define XYZ_B_STRIDE 393216

__device__ float g_sum1[16], g_ss1[16];
__device__ float g_bn1_scale[16], g_bn1_bias[16];
__device__ float g_osum[64], g_oss[64];
__device__ float g_obn_scale[64], g_obn_bias[64];

// weightbank split into bf16 hi/lo, same [ci][512] layout
__device__ __nv_bfloat16 g_Bh[32768];
__device__ __nv_bfloat16 g_Bl[32768];

__device__ __forceinline__ uint32_t cvt_bf16x2_pack(float hi_val, float lo_val) {
    uint32_t r; asm("cvt.rn.bf16x2.f32 %0, %1, %2;" : "=r"(r) : "f"(hi_val), "f"(lo_val)); return r;
}
__device__ __forceinline__ uint32_t smem_u32(const void* p) {
    uint32_t a;
    asm("{ .reg .u64 t; cvta.to.shared.u64 t, %1; cvt.u32.u64 %0, t; }" : "=r"(a) : "l"(p));
    return a;
}
__device__ __forceinline__ void ldsm4t(uint32_t* r, uint32_t addr) {
    asm volatile("ldmatrix.sync.aligned.m8n8.x4.trans.shared.b16 {%0,%1,%2,%3}, [%4];"
                 : "=r"(r[0]), "=r"(r[1]), "=r"(r[2]), "=r"(r[3]) : "r"(addr));
}
__device__ __forceinline__ void mma16816(float* c, const uint32_t* a, uint32_t b0, uint32_t b1) {
    asm volatile("mma.sync.aligned.m16n8k16.row.col.f32.bf16.bf16.f32 "
                 "{%0,%1,%2,%3}, {%4,%5,%6,%7}, {%8,%9}, {%0,%1,%2,%3};"
                 : "+f"(c[0]), "+f"(c[1]), "+f"(c[2]), "+f"(c[3])
                 : "r"(a[0]), "r"(a[1]), "r"(a[2]), "r"(a[3]), "r"(b0), "r"(b1));
}

// ---------------- K0: zero stat accumulators ----------------
__global__ void k0_zero() {
    int i = threadIdx.x;
    if (i < 16) { g_sum1[i] = 0.f; g_ss1[i] = 0.f; }
    if (i < 64) { g_osum[i] = 0.f; g_oss[i] = 0.f; }
}

// ---------------- KP: split weightbank into bf16 hi/lo ----------------
__global__ void kp_splitW(const float* __restrict__ wbank) {
    int idx = blockIdx.x * 512 + threadIdx.x;
    float w = wbank[idx];
    __nv_bfloat16 hb = __float2bfloat16(w);
    g_Bh[idx] = hb;
    g_Bl[idx] = __float2bfloat16(w - __bfloat162float(hb));
}

// ---------------- K1: ScoreNet conv1 BN stats ----------------
__global__ void k1_stats(const float* __restrict__ gxyz, const float* __restrict__ w1) {
    __shared__ float sw1[64];
    if (threadIdx.x < 64) sw1[threadIdx.x] = w1[threadIdx.x];
    __syncthreads();
    float s[16], q[16];
#pragma unroll
    for (int o = 0; o < 16; ++o) { s[o] = 0.f; q[o] = 0.f; }
    int gtid = blockIdx.x * 512 + threadIdx.x;
#pragma unroll
    for (int i = 0; i < 8; ++i) {
        int p = gtid + i * 65536;
        int b = p >> 17;
        int rem = p & 131071;
        const float* gp = gxyz + (size_t)b * XYZ_B_STRIDE + rem;
        float x = gp[0], y = gp[FEAT_CI_STRIDE], z = gp[2 * FEAT_CI_STRIDE];
        float ed = sqrtf(x * x + y * y + z * z);
#pragma unroll
        for (int o = 0; o < 16; ++o) {
            float v = sw1[o * 4] * x + sw1[o * 4 + 1] * y + sw1[o * 4 + 2] * z + sw1[o * 4 + 3] * ed;
            s[o] += v; q[o] += v * v;
        }
    }
#pragma unroll
    for (int o = 0; o < 16; ++o) {
#pragma unroll
        for (int off = 16; off; off >>= 1) {
            s[o] += __shfl_xor_sync(0xFFFFFFFFu, s[o], off);
            q[o] += __shfl_xor_sync(0xFFFFFFFFu, q[o], off);
        }
    }
    if ((threadIdx.x & 31) == 0) {
#pragma unroll
        for (int o = 0; o < 16; ++o) { atomicAdd(&g_sum1[o], s[o]); atomicAdd(&g_ss1[o], q[o]); }
    }
}

__global__ void k1b_fold(const float* __restrict__ g1, const float* __restrict__ b1) {
    int i = threadIdx.x;
    if (i < 16) {
        const float P = (float)NPTS;
        float mean = g_sum1[i] / P;
        float var = g_ss1[i] / P - mean * mean;
        float sc = rsqrtf(var + 1e-5f) * g1[i];
        g_bn1_scale[i] = sc;
        g_bn1_bias[i] = b1[i] - mean * sc;
    }
}

// ---------------- K2: raw-MMA main kernel ----------------
// SMEM (bytes):
//   A hi [64ci][136p] bf16 : 17408 @ 0        (aliased by out-transpose buf [64c][132p] f32)
//   A lo                   : 17408 @ 17408
//   B 2 bufs x (hi+lo) [64ci][88n] bf16 : 4 x 11264 @ 34816
//   scores [128p][8m] f32  :  4096 @ 79872
//   stats 128 f32          :   512 @ 83968
#define LDA 136
#define LDB 88
#define OFF_AH 0
#define OFF_AL 17408
#define OFF_B  34816
#define OFF_S  79872
#define OFF_STAT 83968
#define SMEM_SZ 84480

__global__ __launch_bounds__(256, 2)
void k2_mma(const float* __restrict__ gxyz, const float* __restrict__ feat,
            const float* __restrict__ w1, const float* __restrict__ w2,
            const float* __restrict__ b2, float* __restrict__ outp) {
    extern __shared__ char smem[];
    const uint32_t sbase = smem_u32(smem);
    float* sS = (float*)(smem + OFF_S);
    float* sSum = (float*)(smem + OFF_STAT);
    float* sSS  = sSum + 64;

    const int tid = threadIdx.x;
    const int wid = tid >> 5;
    const int lane = tid & 31;
    const int gg0 = blockIdx.x * 4;
    const int b = gg0 >> 12;
    const int n0 = gg0 & 4095;

    if (tid < 64) { sSum[tid] = 0.f; sSS[tid] = 0.f; }

    // ---- form A hi/lo [ci][136 p] from global feature (coalesced) ----
    const float* fb = feat + ((size_t)b << 23) + n0 * 32;
    for (int idx = tid; idx < 2048; idx += 256) {
        int ci = idx >> 5, p4 = idx & 31;
        float4 v = ((const float4*)(fb + (size_t)ci * FEAT_CI_STRIDE))[p4];
        uint32_t h0 = cvt_bf16x2_pack(v.y, v.x);
        uint32_t h1 = cvt_bf16x2_pack(v.w, v.z);
        float2 f0 = __bfloat1622float2(*(__nv_bfloat162*)&h0);
        float2 f1 = __bfloat1622float2(*(__nv_bfloat162*)&h1);
        uint32_t l0 = cvt_bf16x2_pack(v.y - f0.y, v.x - f0.x);
        uint32_t l1 = cvt_bf16x2_pack(v.w - f1.y, v.z - f1.x);
        *(uint2*)(smem + OFF_AH + ci * (LDA * 2) + p4 * 8) = make_uint2(h0, h1);
        *(uint2*)(smem + OFF_AL + ci * (LDA * 2) + p4 * 8) = make_uint2(l0, l1);
    }

    // ---- scores for 128 points ----
    if (tid < 128) {
        int g = tid >> 5, kk = tid & 31;
        int n = n0 + g;
        const float* gp = gxyz + (size_t)b * XYZ_B_STRIDE + n * 32 + kk;
        float x = gp[0], y = gp[FEAT_CI_STRIDE], z = gp[2 * FEAT_CI_STRIDE];
        float ed = sqrtf(x * x + y * y + z * z);
        float h[16];
#pragma unroll
        for (int o = 0; o < 16; ++o) {
            float v = w1[o * 4] * x + w1[o * 4 + 1] * y + w1[o * 4 + 2] * z + w1[o * 4 + 3] * ed;
            h[o] = fmaxf(fmaf(v, g_bn1_scale[o], g_bn1_bias[o]), 0.f);
        }
        float sv[8], mx = -1e30f;
#pragma unroll
        for (int j = 0; j < 8; ++j) {
            float a = b2[j];
#pragma unroll
            for (int o = 0; o < 16; ++o) a = fmaf(w2[j * 16 + o], h[o], a);
            sv[j] = a; mx = fmaxf(mx, a);
        }
        float den = 1.f;
#pragma unroll
        for (int j = 0; j < 8; ++j) { sv[j] = expf(sv[j] - mx); den += sv[j]; }
        float rden = 1.f / den;
#pragma unroll
        for (int j = 0; j < 8; ++j) sS[tid * 8 + j] = sv[j] * rden;
    }

    // B copy helper: chunk m -> buffer buf (hi then lo)
    auto copyB = [&](int m, int buf) {
        char* dst0 = smem + OFF_B + buf * 22528;
#pragma unroll
        for (int t4 = 0; t4 < 4; ++t4) {
            int t = tid + t4 * 256;          // 0..1023
            int prec = t >> 9;
            int row = (t >> 3) & 63;
            int seg = t & 7;
            const char* src = (const char*)(prec ? g_Bl : g_Bh) + (size_t)row * 1024 + m * 128 + seg * 16;
            *(uint4*)(dst0 + prec * 11264 + row * (LDB * 2) + seg * 16) =
                *(const uint4*)src;
        }
    };

    copyB(0, 0);
    __syncthreads();   // A, scores, B[0] ready

    // warp tiling: 4 warps in p (32 rows each), 2 warps in n (32 cols each)
    const int wp = (wid & 3) * 32;
    const int wn = (wid >> 2) * 32;
    const int lr = lane & 7;
    const int mi = lane >> 3;
    // ldmatrix.x4.trans address offsets (elements):
    // A: m0=(k0-7,p0-7) m1=(k0-7,p8-15) m2=(k8-15,p0-7) m3=(k8-15,p8-15)
    const uint32_t aoff = (uint32_t)(((mi >> 1) * 8 + lr) * LDA + wp + (mi & 1) * 8);
    // B: m0=(k0-7,n0-7) m1=(k8-15,n0-7) m2=(k0-7,n8-15) m3=(k8-15,n8-15)
    const uint32_t boff = (uint32_t)(((mi & 1) * 8 + lr) * LDB + wn + (mi >> 1) * 8);

    float out[2][4][4];
#pragma unroll
    for (int i = 0; i < 2; ++i)
#pragma unroll
        for (int j = 0; j < 4; ++j)
#pragma unroll
            for (int e = 0; e < 4; ++e) out[i][j][e] = 0.f;

    for (int m = 0; m < 8; ++m) {
        if (m < 7) copyB(m + 1, (m + 1) & 1);
        const uint32_t bH = sbase + OFF_B + (m & 1) * 22528;
        const uint32_t bL = bH + 11264;

        float acc[2][4][4];
#pragma unroll
        for (int i = 0; i < 2; ++i)
#pragma unroll
            for (int j = 0; j < 4; ++j)
#pragma unroll
                for (int e = 0; e < 4; ++e) acc[i][j][e] = 0.f;

#pragma unroll
        for (int ks = 0; ks < 4; ++ks) {
            const int k0 = ks * 16;
            uint32_t ah[2][4], al[2][4], bh[2][4], bl[2][4];
#pragma unroll
            for (int i = 0; i < 2; ++i) {
                uint32_t ao = (aoff + (uint32_t)(k0 * LDA + i * 16)) * 2;
                ldsm4t(ah[i], sbase + OFF_AH + ao);
                ldsm4t(al[i], sbase + OFF_AL + ao);
            }
#pragma unroll
            for (int u = 0; u < 2; ++u) {
                uint32_t bo = (boff + (uint32_t)(k0 * LDB + u * 16)) * 2;
                ldsm4t(bh[u], bH + bo);
                ldsm4t(bl[u], bL + bo);
            }
#pragma unroll
            for (int i = 0; i < 2; ++i)
#pragma unroll
                for (int u = 0; u < 2; ++u)
#pragma unroll
                    for (int v = 0; v < 2; ++v) {
                        float* a4 = acc[i][u * 2 + v];
                        mma16816(a4, ah[i], bh[u][2 * v], bh[u][2 * v + 1]);
                        mma16816(a4, ah[i], bl[u][2 * v], bl[u][2 * v + 1]);
                        mma16816(a4, al[i], bh[u][2 * v], bh[u][2 * v + 1]);
                    }
        }

        // in-register score combine: out += s[p][m] * acc
#pragma unroll
        for (int i = 0; i < 2; ++i) {
            int pr = wp + i * 16 + (lane >> 2);
            float s0 = sS[pr * 8 + m];
            float s1 = sS[(pr + 8) * 8 + m];
#pragma unroll
            for (int j = 0; j < 4; ++j) {
                out[i][j][0] = fmaf(s0, acc[i][j][0], out[i][j][0]);
                out[i][j][1] = fmaf(s0, acc[i][j][1], out[i][j][1]);
                out[i][j][2] = fmaf(s1, acc[i][j][2], out[i][j][2]);
                out[i][j][3] = fmaf(s1, acc[i][j][3], out[i][j][3]);
            }
        }
        __syncthreads();   // all warps done with buf[m&1] before it is refilled at m+2
    }

    // ---- epilogue: registers -> smem [64c][132p] (aliases A) -> coalesced STG ----
    float* tb = (float*)smem;
#pragma unroll
    for (int i = 0; i < 2; ++i) {
        int pr = wp + i * 16 + (lane >> 2);
#pragma unroll
        for (int j = 0; j < 4; ++j) {
            int c0 = wn + j * 8 + (lane & 3) * 2;
            tb[c0 * 132 + pr]           = out[i][j][0];
            tb[(c0 + 1) * 132 + pr]     = out[i][j][1];
            tb[c0 * 132 + pr + 8]       = out[i][j][2];
            tb[(c0 + 1) * 132 + pr + 8] = out[i][j][3];
        }
    }
    __syncthreads();

#pragma unroll
    for (int ii = 0; ii < 8; ++ii) {
        int cc = wid * 8 + ii;
        float4 v = *(const float4*)(tb + cc * 132 + lane * 4);
        float su = v.x + v.y + v.z + v.w;
        float sq = v.x * v.x + v.y * v.y + v.z * v.z + v.w * v.w;
#pragma unroll
        for (int off = 16; off; off >>= 1) {
            su += __shfl_xor_sync(0xFFFFFFFFu, su, off);
            sq += __shfl_xor_sync(0xFFFFFFFFu, sq, off);
        }
        if (lane == 0) { atomicAdd(&sSum[cc], su); atomicAdd(&sSS[cc], sq); }
        ((float4*)(outp + ((size_t)b * 64 + cc) * 131072 + n0 * 32))[lane] = v;
    }
    __syncthreads();
    if (tid < 64) { atomicAdd(&g_osum[tid], sSum[tid]); atomicAdd(&g_oss[tid], sSS[tid]); }
}

// ---------------- K2b: fold output BN ----------------
__global__ void k2b_fold(const float* __restrict__ gout, const float* __restrict__ bout) {
    int i = threadIdx.x;
    if (i < 64) {
        const float P = (float)NPTS;
        float mean = g_osum[i] / P;
        float var = g_oss[i] / P - mean * mean;
        float sc = rsqrtf(var + 1e-5f) * gout[i];
        g_obn_scale[i] = sc;
        g_obn_bias[i] = bout[i] - mean * sc;
    }
}

// ---------------- K3: apply BN + ReLU in place ----------------
__global__ void k3_bnrelu(float* __restrict__ outp) {
    const int total4 = 8388608;
    int stride = gridDim.x * blockDim.x;
    for (int idx = blockIdx.x * blockDim.x + threadIdx.x; idx < total4; idx += stride) {
        int cch = (idx >> 15) & 63;
        float sc = g_obn_scale[cch], bi = g_obn_bias[cch];
        float4 v = ((const float4*)outp)[idx];
        v.x = fmaxf(fmaf(v.x, sc, bi), 0.f);
        v.y = fmaxf(fmaf(v.y, sc, bi), 0.f);
        v.z = fmaxf(fmaf(v.z, sc, bi), 0.f);
        v.w = fmaxf(fmaf(v.w, sc, bi), 0.f);
        ((float4*)outp)[idx] = v;
    }
}

extern "C" void kernel_launch(void* const* d_in, const int* in_sizes, int n_in,
                              void* d_out, int out_size) {
    const float* gxyz  = (const float*)d_in[0];
    const float* feat  = (const float*)d_in[1];
    const float* w1    = (const float*)d_in[2];
    const float* g1    = (const float*)d_in[3];
    const float* b1    = (const float*)d_in[4];
    const float* w2    = (const float*)d_in[5];
    const float* b2    = (const float*)d_in[6];
    const float* wbank = (const float*)d_in[7];
    const float* gout  = (const float*)d_in[8];
    const float* bout  = (const float*)d_in[9];
    float* outp = (float*)d_out;

    cudaFuncSetAttribute(k2_mma, cudaFuncAttributeMaxDynamicSharedMemorySize, SMEM_SZ);

    k0_zero<<<1, 64>>>();
    kp_splitW<<<64, 512>>>(wbank);
    k1_stats<<<128, 512>>>(gxyz, w1);
    k1b_fold<<<1, 16>>>(g1, b1);
    k2_mma<<<4096, 256, SMEM_SZ>>>(gxyz, feat, w1, w2, b2, outp);
    k2b_fold<<<1, 64>>>(gout, bout);
    k3_bnrelu<<<2048, 512>>>(outp);
}

// round 15
// speedup vs baseline: 4.9636x; 1.0583x over previous
#include <cuda_runtime.h>
#include <cuda_bf16.h>
#include <math.h>
#include <cstdint>

// B=4, N=4096, k=32, Cin=64, Cout=64, M=8 ; P = 524288 points
// Stage 1 (mma.sync bf16 hi/lo x3): proj_m[p][c] = sum_ci f[p][ci] * W[ci][m*64+c]
// Stage 2 (in-register): out[p][c] = sum_m s[p][m] * proj_m[p][c]

#define NPTS 524288
#define FEAT_CI_STRIDE 131072
#define XYZ_B_STRIDE 393216

__device__ float g_sum1[16], g_ss1[16];
__device__ float g_osum[64], g_oss[64];

// weightbank split into bf16 hi/lo, [ci][512] layout
__device__ __nv_bfloat16 g_Bh[32768];
__device__ __nv_bfloat16 g_Bl[32768];

__device__ __forceinline__ uint32_t cvt_bf16x2_pack(float hi_val, float lo_val) {
    uint32_t r; asm("cvt.rn.bf16x2.f32 %0, %1, %2;" : "=r"(r) : "f"(hi_val), "f"(lo_val)); return r;
}
__device__ __forceinline__ uint32_t smem_u32(const void* p) {
    uint32_t a;
    asm("{ .reg .u64 t; cvta.to.shared.u64 t, %1; cvt.u32.u64 %0, t; }" : "=r"(a) : "l"(p));
    return a;
}
__device__ __forceinline__ void ldsm4t(uint32_t* r, uint32_t addr) {
    asm volatile("ldmatrix.sync.aligned.m8n8.x4.trans.shared.b16 {%0,%1,%2,%3}, [%4];"
                 : "=r"(r[0]), "=r"(r[1]), "=r"(r[2]), "=r"(r[3]) : "r"(addr));
}
__device__ __forceinline__ void mma16816(float* c, const uint32_t* a, uint32_t b0, uint32_t b1) {
    asm volatile("mma.sync.aligned.m16n8k16.row.col.f32.bf16.bf16.f32 "
                 "{%0,%1,%2,%3}, {%4,%5,%6,%7}, {%8,%9}, {%0,%1,%2,%3};"
                 : "+f"(c[0]), "+f"(c[1]), "+f"(c[2]), "+f"(c[3])
                 : "r"(a[0]), "r"(a[1]), "r"(a[2]), "r"(a[3]), "r"(b0), "r"(b1));
}
__device__ __forceinline__ void cpa16(uint32_t dst, const void* src) {
    asm volatile("cp.async.cg.shared.global [%0], [%1], 16;" :: "r"(dst), "l"(src) : "memory");
}
__device__ __forceinline__ void cpa_commit() { asm volatile("cp.async.commit_group;" ::: "memory"); }
__device__ __forceinline__ void cpa_wait0()  { asm volatile("cp.async.wait_group 0;" ::: "memory"); }

// ---------------- K0: zero stat accumulators ----------------
__global__ void k0_zero() {
    int i = threadIdx.x;
    if (i < 16) { g_sum1[i] = 0.f; g_ss1[i] = 0.f; }
    if (i < 64) { g_osum[i] = 0.f; g_oss[i] = 0.f; }
}

// ---------------- K1: weightbank split (blocks 0-63) + ScoreNet conv1 BN stats ----------------
__global__ void k1_stats(const float* __restrict__ gxyz, const float* __restrict__ w1,
                         const float* __restrict__ wbank) {
    // merged KP: split weightbank into bf16 hi/lo
    if (blockIdx.x < 64) {
        int idx = blockIdx.x * 512 + threadIdx.x;
        float w = wbank[idx];
        __nv_bfloat16 hb = __float2bfloat16(w);
        g_Bh[idx] = hb;
        g_Bl[idx] = __float2bfloat16(w - __bfloat162float(hb));
    }

    __shared__ float sw1[64];
    if (threadIdx.x < 64) sw1[threadIdx.x] = w1[threadIdx.x];
    __syncthreads();
    float s[16], q[16];
#pragma unroll
    for (int o = 0; o < 16; ++o) { s[o] = 0.f; q[o] = 0.f; }
    int gtid = blockIdx.x * 512 + threadIdx.x;
#pragma unroll
    for (int i = 0; i < 8; ++i) {
        int p = gtid + i * 65536;
        int b = p >> 17;
        int rem = p & 131071;
        const float* gp = gxyz + (size_t)b * XYZ_B_STRIDE + rem;
        float x = gp[0], y = gp[FEAT_CI_STRIDE], z = gp[2 * FEAT_CI_STRIDE];
        float ed = sqrtf(x * x + y * y + z * z);
#pragma unroll
        for (int o = 0; o < 16; ++o) {
            float v = sw1[o * 4] * x + sw1[o * 4 + 1] * y + sw1[o * 4 + 2] * z + sw1[o * 4 + 3] * ed;
            s[o] += v; q[o] += v * v;
        }
    }
#pragma unroll
    for (int o = 0; o < 16; ++o) {
#pragma unroll
        for (int off = 16; off; off >>= 1) {
            s[o] += __shfl_xor_sync(0xFFFFFFFFu, s[o], off);
            q[o] += __shfl_xor_sync(0xFFFFFFFFu, q[o], off);
        }
    }
    if ((threadIdx.x & 31) == 0) {
#pragma unroll
        for (int o = 0; o < 16; ++o) { atomicAdd(&g_sum1[o], s[o]); atomicAdd(&g_ss1[o], q[o]); }
    }
}

// ---------------- K2: raw-MMA main kernel, 256-point tiles ----------------
// SMEM (bytes):
//   A hi [64ci][264p] bf16 : 33792 @ 0      (hi+lo aliased by out buf [64c][268p] f32 = 68608)
//   A lo                   : 33792 @ 33792
//   B 2 bufs x (hi+lo) [64ci][88n] bf16 : 4 x 11264 @ 67584
//   scores [256p][8m] f32  :  8192 @ 112640
//   stats 128 f32          :   512 @ 120832
//   bn1 fold 32 f32        :   128 @ 121344
#define LDA 264
#define LDB 88
#define LDT 268
#define OFF_AH 0
#define OFF_AL 33792
#define OFF_B  67584
#define OFF_S  112640
#define OFF_STAT 120832
#define OFF_F  121344
#define SMEM_SZ 121472

__global__ __launch_bounds__(512, 1)
void k2_mma(const float* __restrict__ gxyz, const float* __restrict__ feat,
            const float* __restrict__ w1, const float* __restrict__ w2,
            const float* __restrict__ b2, const float* __restrict__ g1,
            const float* __restrict__ b1, float* __restrict__ outp) {
    extern __shared__ char smem[];
    const uint32_t sbase = smem_u32(smem);
    float* sS = (float*)(smem + OFF_S);
    float* sSum = (float*)(smem + OFF_STAT);
    float* sSS  = sSum + 64;
    float* sF   = (float*)(smem + OFF_F);

    const int tid = threadIdx.x;
    const int wid = tid >> 5;
    const int lane = tid & 31;
    const int gg0 = blockIdx.x * 8;       // 8 groups = 256 points per block
    const int b = gg0 >> 12;
    const int n0 = gg0 & 4095;

    // merged k1b fold (per-block, cheap)
    if (tid < 16) {
        const float P = (float)NPTS;
        float mean = g_sum1[tid] / P;
        float var = g_ss1[tid] / P - mean * mean;
        float sc = rsqrtf(var + 1e-5f) * g1[tid];
        sF[tid] = sc;
        sF[16 + tid] = b1[tid] - mean * sc;
    }
    if (tid < 64) { sSum[tid] = 0.f; sSS[tid] = 0.f; }

    // B copy helper: chunk m -> buffer buf via cp.async (1024 x 16B chunks)
    auto copyB = [&](int m, int buf) {
        uint32_t dst0 = sbase + OFF_B + buf * 22528;
#pragma unroll
        for (int t2 = 0; t2 < 2; ++t2) {
            int q = tid + t2 * 512;
            int prec = q >> 9;
            int row = (q >> 3) & 63;
            int seg = q & 7;
            const char* src = (const char*)(prec ? g_Bl : g_Bh) + (size_t)row * 1024 + m * 128 + seg * 16;
            cpa16(dst0 + prec * 11264 + row * (LDB * 2) + seg * 16, src);
        }
    };

    copyB(0, 0);
    cpa_commit();

    // ---- form A hi/lo [ci][264 p] from global feature (coalesced) ----
    const float* fb = feat + ((size_t)b << 23) + n0 * 32;
#pragma unroll
    for (int t8 = 0; t8 < 8; ++t8) {
        int idx = tid + t8 * 512;          // 0..4095
        int ci = idx >> 6, p4 = idx & 63;
        float4 v = ((const float4*)(fb + (size_t)ci * FEAT_CI_STRIDE))[p4];
        uint32_t h0 = cvt_bf16x2_pack(v.y, v.x);
        uint32_t h1 = cvt_bf16x2_pack(v.w, v.z);
        float2 f0 = __bfloat1622float2(*(__nv_bfloat162*)&h0);
        float2 f1 = __bfloat1622float2(*(__nv_bfloat162*)&h1);
        uint32_t l0 = cvt_bf16x2_pack(v.y - f0.y, v.x - f0.x);
        uint32_t l1 = cvt_bf16x2_pack(v.w - f1.y, v.z - f1.x);
        *(uint2*)(smem + OFF_AH + ci * (LDA * 2) + p4 * 8) = make_uint2(h0, h1);
        *(uint2*)(smem + OFF_AL + ci * (LDA * 2) + p4 * 8) = make_uint2(l0, l1);
    }
    __syncthreads();   // sF ready for scores; A stores still pending until next sync

    // ---- scores for 256 points ----
    if (tid < 256) {
        int g = tid >> 5, kk = tid & 31;
        int n = n0 + g;
        const float* gp = gxyz + (size_t)b * XYZ_B_STRIDE + n * 32 + kk;
        float x = gp[0], y = gp[FEAT_CI_STRIDE], z = gp[2 * FEAT_CI_STRIDE];
        float ed = sqrtf(x * x + y * y + z * z);
        float h[16];
#pragma unroll
        for (int o = 0; o < 16; ++o) {
            float v = w1[o * 4] * x + w1[o * 4 + 1] * y + w1[o * 4 + 2] * z + w1[o * 4 + 3] * ed;
            h[o] = fmaxf(fmaf(v, sF[o], sF[16 + o]), 0.f);
        }
        float sv[8], mx = -1e30f;
#pragma unroll
        for (int j = 0; j < 8; ++j) {
            float a = b2[j];
#pragma unroll
            for (int o = 0; o < 16; ++o) a = fmaf(w2[j * 16 + o], h[o], a);
            sv[j] = a; mx = fmaxf(mx, a);
        }
        float den = 1.f;
#pragma unroll
        for (int j = 0; j < 8; ++j) { sv[j] = expf(sv[j] - mx); den += sv[j]; }
        float rden = 1.f / den;
#pragma unroll
        for (int j = 0; j < 8; ++j) sS[tid * 8 + j] = sv[j] * rden;
    }
    cpa_wait0();
    __syncthreads();   // A, scores, B[0] all visible

    // warp tiling: 8 warps in p (32 rows each), 2 warps in n (32 cols each)
    const int wp = (wid & 7) * 32;
    const int wn = (wid >> 3) * 32;
    const int lr = lane & 7;
    const int mi = lane >> 3;
    const uint32_t aoff = (uint32_t)(((mi >> 1) * 8 + lr) * LDA + wp + (mi & 1) * 8);
    const uint32_t boff = (uint32_t)(((mi & 1) * 8 + lr) * LDB + wn + (mi >> 1) * 8);

    float out[2][4][4];
#pragma unroll
    for (int i = 0; i < 2; ++i)
#pragma unroll
        for (int j = 0; j < 4; ++j)
#pragma unroll
            for (int e = 0; e < 4; ++e) out[i][j][e] = 0.f;

    for (int m = 0; m < 8; ++m) {
        if (m < 7) { copyB(m + 1, (m + 1) & 1); cpa_commit(); }
        const uint32_t bH = sbase + OFF_B + (m & 1) * 22528;
        const uint32_t bL = bH + 11264;

        float acc[2][4][4];
#pragma unroll
        for (int i = 0; i < 2; ++i)
#pragma unroll
            for (int j = 0; j < 4; ++j)
#pragma unroll
                for (int e = 0; e < 4; ++e) acc[i][j][e] = 0.f;

#pragma unroll
        for (int ks = 0; ks < 4; ++ks) {
            const int k0 = ks * 16;
            uint32_t ah[2][4], al[2][4], bh[2][4], bl[2][4];
#pragma unroll
            for (int i = 0; i < 2; ++i) {
                uint32_t ao = (aoff + (uint32_t)(k0 * LDA + i * 16)) * 2;
                ldsm4t(ah[i], sbase + OFF_AH + ao);
                ldsm4t(al[i], sbase + OFF_AL + ao);
            }
#pragma unroll
            for (int u = 0; u < 2; ++u) {
                uint32_t bo = (boff + (uint32_t)(k0 * LDB + u * 16)) * 2;
                ldsm4t(bh[u], bH + bo);
                ldsm4t(bl[u], bL + bo);
            }
#pragma unroll
            for (int i = 0; i < 2; ++i)
#pragma unroll
                for (int u = 0; u < 2; ++u)
#pragma unroll
                    for (int v = 0; v < 2; ++v) {
                        float* a4 = acc[i][u * 2 + v];
                        mma16816(a4, ah[i], bh[u][2 * v], bh[u][2 * v + 1]);
                        mma16816(a4, ah[i], bl[u][2 * v], bl[u][2 * v + 1]);
                        mma16816(a4, al[i], bh[u][2 * v], bh[u][2 * v + 1]);
                    }
        }

        // in-register score combine: out += s[p][m] * acc
#pragma unroll
        for (int i = 0; i < 2; ++i) {
            int pr = wp + i * 16 + (lane >> 2);
            float s0 = sS[pr * 8 + m];
            float s1 = sS[(pr + 8) * 8 + m];
#pragma unroll
            for (int j = 0; j < 4; ++j) {
                out[i][j][0] = fmaf(s0, acc[i][j][0], out[i][j][0]);
                out[i][j][1] = fmaf(s0, acc[i][j][1], out[i][j][1]);
                out[i][j][2] = fmaf(s1, acc[i][j][2], out[i][j][2]);
                out[i][j][3] = fmaf(s1, acc[i][j][3], out[i][j][3]);
            }
        }
        cpa_wait0();
        __syncthreads();   // buf for m+1 ready; all warps done reading buf m
    }

    // ---- epilogue: registers -> smem [64c][268p] (aliases A) -> coalesced STG ----
    float* tb = (float*)smem;
#pragma unroll
    for (int i = 0; i < 2; ++i) {
        int pr = wp + i * 16 + (lane >> 2);
#pragma unroll
        for (int j = 0; j < 4; ++j) {
            int c0 = wn + j * 8 + (lane & 3) * 2;
            tb[c0 * LDT + pr]           = out[i][j][0];
            tb[(c0 + 1) * LDT + pr]     = out[i][j][1];
            tb[c0 * LDT + pr + 8]       = out[i][j][2];
            tb[(c0 + 1) * LDT + pr + 8] = out[i][j][3];
        }
    }
    __syncthreads();

#pragma unroll
    for (int ii = 0; ii < 4; ++ii) {
        int cc = (wid << 2) + ii;
        float4 v1 = *(const float4*)(tb + cc * LDT + lane * 4);
        float4 v2 = *(const float4*)(tb + cc * LDT + 128 + lane * 4);
        float su = v1.x + v1.y + v1.z + v1.w + v2.x + v2.y + v2.z + v2.w;
        float sq = v1.x * v1.x + v1.y * v1.y + v1.z * v1.z + v1.w * v1.w
                 + v2.x * v2.x + v2.y * v2.y + v2.z * v2.z + v2.w * v2.w;
#pragma unroll
        for (int off = 16; off; off >>= 1) {
            su += __shfl_xor_sync(0xFFFFFFFFu, su, off);
            sq += __shfl_xor_sync(0xFFFFFFFFu, sq, off);
        }
        if (lane == 0) { atomicAdd(&sSum[cc], su); atomicAdd(&sSS[cc], sq); }
        float4* ob = (float4*)(outp + ((size_t)b * 64 + cc) * 131072 + n0 * 32);
        ob[lane] = v1;
        ob[lane + 32] = v2;
    }
    __syncthreads();
    if (tid < 64) { atomicAdd(&g_osum[tid], sSum[tid]); atomicAdd(&g_oss[tid], sSS[tid]); }
}

// ---------------- K3: fold output BN (per-block) + apply BN + ReLU in place ----------------
__global__ void k3_bnrelu(float* __restrict__ outp, const float* __restrict__ gout,
                          const float* __restrict__ bout) {
    __shared__ float ssc[64], sbi[64];
    if (threadIdx.x < 64) {
        int i = threadIdx.x;
        const float P = (float)NPTS;
        float mean = g_osum[i] / P;
        float var = g_oss[i] / P - mean * mean;
        float sc = rsqrtf(var + 1e-5f) * gout[i];
        ssc[i] = sc;
        sbi[i] = bout[i] - mean * sc;
    }
    __syncthreads();
    const int total4 = 8388608;
    int stride = gridDim.x * blockDim.x;
    for (int idx = blockIdx.x * blockDim.x + threadIdx.x; idx < total4; idx += stride) {
        int cch = (idx >> 15) & 63;
        float sc = ssc[cch], bi = sbi[cch];
        float4 v = ((const float4*)outp)[idx];
        v.x = fmaxf(fmaf(v.x, sc, bi), 0.f);
        v.y = fmaxf(fmaf(v.y, sc, bi), 0.f);
        v.z = fmaxf(fmaf(v.z, sc, bi), 0.f);
        v.w = fmaxf(fmaf(v.w, sc, bi), 0.f);
        ((float4*)outp)[idx] = v;
    }
}

extern "C" void kernel_launch(void* const* d_in, const int* in_sizes, int n_in,
                              void* d_out, int out_size) {
    const float* gxyz  = (const float*)d_in[0];
    const float* feat  = (const float*)d_in[1];
    const float* w1    = (const float*)d_in[2];
    const float* g1    = (const float*)d_in[3];
    const float* b1    = (const float*)d_in[4];
    const float* w2    = (const float*)d_in[5];
    const float* b2    = (const float*)d_in[6];
    const float* wbank = (const float*)d_in[7];
    const float* gout  = (const float*)d_in[8];
    const float* bout  = (const float*)d_in[9];
    float* outp = (float*)d_out;

    cudaFuncSetAttribute(k2_mma, cudaFuncAttributeMaxDynamicSharedMemorySize, SMEM_SZ);

    k0_zero<<<1, 64>>>();
    k1_stats<<<128, 512>>>(gxyz, w1, wbank);
    k2_mma<<<2048, 512, SMEM_SZ>>>(gxyz, feat, w1, w2, b2, g1, b1, outp);
    k3_bnrelu<<<2048, 512>>>(outp, gout, bout);
}

// round 17
// speedup vs baseline: 5.1647x; 1.0405x over previous
#include <cuda_runtime.h>
#include <cuda_bf16.h>
#include <math.h>
#include <cstdint>

// B=4, N=4096, k=32, Cin=64, Cout=64, M=8 ; P = 524288 points
// Stage 1 (mma.sync bf16 hi/lo x3): proj_m[p][c] = sum_ci f[p][ci] * W[ci][m*64+c]
// Stage 2 (in-register): out[p][c] = sum_m s[p][m] * proj_m[p][c]
// Persistent CTAs; full split weightbank resident in SMEM.

#define NPTS 524288
#define FEAT_CI_STRIDE 131072
#define XYZ_B_STRIDE 393216
#define NTILES 2048

__device__ float g_sum1[16], g_ss1[16];
__device__ float g_osum[64], g_oss[64];

// weightbank split into bf16 hi/lo, [ci][512] layout
__device__ __nv_bfloat16 g_Bh[32768];
__device__ __nv_bfloat16 g_Bl[32768];

__device__ __forceinline__ uint32_t cvt_bf16x2_pack(float hi_val, float lo_val) {
    uint32_t r; asm("cvt.rn.bf16x2.f32 %0, %1, %2;" : "=r"(r) : "f"(hi_val), "f"(lo_val)); return r;
}
__device__ __forceinline__ uint32_t smem_u32(const void* p) {
    uint32_t a;
    asm("{ .reg .u64 t; cvta.to.shared.u64 t, %1; cvt.u32.u64 %0, t; }" : "=r"(a) : "l"(p));
    return a;
}
__device__ __forceinline__ void ldsm4t(uint32_t* r, uint32_t addr) {
    asm volatile("ldmatrix.sync.aligned.m8n8.x4.trans.shared.b16 {%0,%1,%2,%3}, [%4];"
                 : "=r"(r[0]), "=r"(r[1]), "=r"(r[2]), "=r"(r[3]) : "r"(addr));
}
__device__ __forceinline__ void mma16816(float* c, const uint32_t* a, uint32_t b0, uint32_t b1) {
    asm volatile("mma.sync.aligned.m16n8k16.row.col.f32.bf16.bf16.f32 "
                 "{%0,%1,%2,%3}, {%4,%5,%6,%7}, {%8,%9}, {%0,%1,%2,%3};"
                 : "+f"(c[0]), "+f"(c[1]), "+f"(c[2]), "+f"(c[3])
                 : "r"(a[0]), "r"(a[1]), "r"(a[2]), "r"(a[3]), "r"(b0), "r"(b1));
}
__device__ __forceinline__ void cpa16(uint32_t dst, const void* src) {
    asm volatile("cp.async.cg.shared.global [%0], [%1], 16;" :: "r"(dst), "l"(src) : "memory");
}
__device__ __forceinline__ void cpa_commit() { asm volatile("cp.async.commit_group;" ::: "memory"); }
__device__ __forceinline__ void cpa_wait0()  { asm volatile("cp.async.wait_group 0;" ::: "memory"); }

// ---------------- K0: zero stat accumulators ----------------
__global__ void k0_zero() {
    int i = threadIdx.x;
    if (i < 16) { g_sum1[i] = 0.f; g_ss1[i] = 0.f; }
    if (i < 64) { g_osum[i] = 0.f; g_oss[i] = 0.f; }
}

// ---------------- K1: weightbank split (blocks 0-63) + ScoreNet conv1 BN stats ----------------
__global__ void k1_stats(const float* __restrict__ gxyz, const float* __restrict__ w1,
                         const float* __restrict__ wbank) {
    if (blockIdx.x < 64) {
        int idx = blockIdx.x * 512 + threadIdx.x;
        float w = wbank[idx];
        __nv_bfloat16 hb = __float2bfloat16(w);
        g_Bh[idx] = hb;
        g_Bl[idx] = __float2bfloat16(w - __bfloat162float(hb));
    }

    __shared__ float sw1[64];
    if (threadIdx.x < 64) sw1[threadIdx.x] = w1[threadIdx.x];
    __syncthreads();
    float s[16], q[16];
#pragma unroll
    for (int o = 0; o < 16; ++o) { s[o] = 0.f; q[o] = 0.f; }
    int gtid = blockIdx.x * 512 + threadIdx.x;
#pragma unroll
    for (int i = 0; i < 8; ++i) {
        int p = gtid + i * 65536;
        int b = p >> 17;
        int rem = p & 131071;
        const float* gp = gxyz + (size_t)b * XYZ_B_STRIDE + rem;
        float x = gp[0], y = gp[FEAT_CI_STRIDE], z = gp[2 * FEAT_CI_STRIDE];
        float ed = sqrtf(x * x + y * y + z * z);
#pragma unroll
        for (int o = 0; o < 16; ++o) {
            float v = sw1[o * 4] * x + sw1[o * 4 + 1] * y + sw1[o * 4 + 2] * z + sw1[o * 4 + 3] * ed;
            s[o] += v; q[o] += v * v;
        }
    }
#pragma unroll
    for (int o = 0; o < 16; ++o) {
#pragma unroll
        for (int off = 16; off; off >>= 1) {
            s[o] += __shfl_xor_sync(0xFFFFFFFFu, s[o], off);
            q[o] += __shfl_xor_sync(0xFFFFFFFFu, q[o], off);
        }
    }
    if ((threadIdx.x & 31) == 0) {
#pragma unroll
        for (int o = 0; o < 16; ++o) { atomicAdd(&g_sum1[o], s[o]); atomicAdd(&g_ss1[o], q[o]); }
    }
}

// ---------------- K2: persistent raw-MMA kernel, resident B, 256-point tiles ----------------
// SMEM (bytes):
//   A region (hi @0 33792, lo @34304 33792) / transpose buf [64c][268p] f32 : 68608 @ 0
//   B resident [8m][2prec][64ci][72n] bf16 (LDB=72, 144B rows) : 147456 @ 68608
//   scores [256p][8m] f32 : 8192 @ 216064
//   bn1 fold 32 f32       :  128 @ 224256
#define LDA 264
#define LDB 72
#define LDT 268
#define OFF_AH 0
#define OFF_AL 34304
#define OFF_B  68608
#define OFF_S  216064
#define OFF_F  224256
#define SMEM_SZ 224384

__global__ __launch_bounds__(512, 1)
void k2_mma(const float* __restrict__ gxyz, const float* __restrict__ feat,
            const float* __restrict__ w1, const float* __restrict__ w2,
            const float* __restrict__ b2, const float* __restrict__ g1,
            const float* __restrict__ b1, float* __restrict__ outp) {
    extern __shared__ char smem[];
    const uint32_t sbase = smem_u32(smem);
    float* sS = (float*)(smem + OFF_S);
    float* sF = (float*)(smem + OFF_F);

    const int tid = threadIdx.x;
    const int wid = tid >> 5;
    const int lane = tid & 31;

    // ---- load full split weightbank into SMEM (once per CTA) ----
#pragma unroll
    for (int i = 0; i < 16; ++i) {
        int q = tid + i * 512;               // 0..8191 16B-chunks
        int m = q >> 10;
        int prec = (q >> 9) & 1;
        int ci = (q >> 3) & 63;
        int seg = q & 7;
        const char* src = (const char*)(prec ? g_Bl : g_Bh) + (size_t)ci * 1024 + m * 128 + seg * 16;
        uint32_t dst = sbase + OFF_B + (uint32_t)(((m * 2 + prec) * 64 + ci) * 144 + seg * 16);
        cpa16(dst, src);
    }
    cpa_commit();

    // bn1 fold (per-CTA, once)
    if (tid < 16) {
        const float P = (float)NPTS;
        float mean = g_sum1[tid] / P;
        float var = g_ss1[tid] / P - mean * mean;
        float sc = rsqrtf(var + 1e-5f) * g1[tid];
        sF[tid] = sc;
        sF[16 + tid] = b1[tid] - mean * sc;
    }

    // warp tiling: 8 warps in p (32 rows each), 2 warps in n (32 cols each)
    const int wp = (wid & 7) * 32;
    const int wn = (wid >> 3) * 32;
    const int lr = lane & 7;
    const int mi = lane >> 3;
    const uint32_t aoff = (uint32_t)(((mi >> 1) * 8 + lr) * LDA + wp + (mi & 1) * 8);
    const uint32_t boffB = (uint32_t)((((mi & 1) * 8 + lr) * LDB + wn + (mi >> 1) * 8) * 2);

    // per-CTA BN stat accumulators (4 channels per warp: cc = wid*4+ii)
    float accsu[4] = {0.f, 0.f, 0.f, 0.f};
    float accsq[4] = {0.f, 0.f, 0.f, 0.f};

    bool firstTile = true;

    for (int t = blockIdx.x; t < NTILES; t += gridDim.x) {
        const int gg0 = t * 8;               // 8 groups = 256 points
        const int b = gg0 >> 12;
        const int n0 = gg0 & 4095;

        __syncthreads();   // prev tile's transpose reads done; A region free

        // ---- form A hi/lo [ci][264 p] from global feature (coalesced) ----
        const float* fb = feat + ((size_t)b << 23) + n0 * 32;
#pragma unroll
        for (int t8 = 0; t8 < 8; ++t8) {
            int idx = tid + t8 * 512;        // 0..4095
            int ci = idx >> 6, p4 = idx & 63;
            float4 v = ((const float4*)(fb + (size_t)ci * FEAT_CI_STRIDE))[p4];
            uint32_t h0 = cvt_bf16x2_pack(v.y, v.x);
            uint32_t h1 = cvt_bf16x2_pack(v.w, v.z);
            float2 f0 = __bfloat1622float2(*(__nv_bfloat162*)&h0);
            float2 f1 = __bfloat1622float2(*(__nv_bfloat162*)&h1);
            uint32_t l0 = cvt_bf16x2_pack(v.y - f0.y, v.x - f0.x);
            uint32_t l1 = cvt_bf16x2_pack(v.w - f1.y, v.z - f1.x);
            *(uint2*)(smem + OFF_AH + ci * (LDA * 2) + p4 * 8) = make_uint2(h0, h1);
            *(uint2*)(smem + OFF_AL + ci * (LDA * 2) + p4 * 8) = make_uint2(l0, l1);
        }

        // ---- scores for 256 points ----
        if (tid < 256) {
            int g = tid >> 5, kk = tid & 31;
            int n = n0 + g;
            const float* gp = gxyz + (size_t)b * XYZ_B_STRIDE + n * 32 + kk;
            float x = gp[0], y = gp[FEAT_CI_STRIDE], z = gp[2 * FEAT_CI_STRIDE];
            float ed = sqrtf(x * x + y * y + z * z);
            float h[16];
#pragma unroll
            for (int o = 0; o < 16; ++o) {
                float v = w1[o * 4] * x + w1[o * 4 + 1] * y + w1[o * 4 + 2] * z + w1[o * 4 + 3] * ed;
                h[o] = fmaxf(fmaf(v, sF[o], sF[16 + o]), 0.f);
            }
            float sv[8], mx = -1e30f;
#pragma unroll
            for (int j = 0; j < 8; ++j) {
                float a = b2[j];
#pragma unroll
                for (int o = 0; o < 16; ++o) a = fmaf(w2[j * 16 + o], h[o], a);
                sv[j] = a; mx = fmaxf(mx, a);
            }
            float den = 1.f;
#pragma unroll
            for (int j = 0; j < 8; ++j) { sv[j] = expf(sv[j] - mx); den += sv[j]; }
            float rden = 1.f / den;
#pragma unroll
            for (int j = 0; j < 8; ++j) sS[tid * 8 + j] = sv[j] * rden;
        }
        if (firstTile) { cpa_wait0(); firstTile = false; }
        __syncthreads();   // A, scores (and resident B on first tile) visible

        float out[2][4][4];
#pragma unroll
        for (int i = 0; i < 2; ++i)
#pragma unroll
            for (int j = 0; j < 4; ++j)
#pragma unroll
                for (int e = 0; e < 4; ++e) out[i][j][e] = 0.f;

        // ---- m-loop: NO barriers (A, B, scores all read-only) ----
        for (int m = 0; m < 8; ++m) {
            const uint32_t bH = sbase + OFF_B + (uint32_t)(m * 18432);
            const uint32_t bL = bH + 9216;

            float acc[2][4][4];
#pragma unroll
            for (int i = 0; i < 2; ++i)
#pragma unroll
                for (int j = 0; j < 4; ++j)
#pragma unroll
                    for (int e = 0; e < 4; ++e) acc[i][j][e] = 0.f;

#pragma unroll
            for (int ks = 0; ks < 4; ++ks) {
                const int k0 = ks * 16;
                uint32_t ah[2][4], al[2][4], bh[2][4], bl[2][4];
#pragma unroll
                for (int i = 0; i < 2; ++i) {
                    uint32_t ao = (aoff + (uint32_t)(k0 * LDA + i * 16)) * 2;
                    ldsm4t(ah[i], sbase + OFF_AH + ao);
                    ldsm4t(al[i], sbase + OFF_AL + ao);
                }
#pragma unroll
                for (int u = 0; u < 2; ++u) {
                    uint32_t bo = boffB + (uint32_t)((k0 * LDB + u * 16) * 2);
                    ldsm4t(bh[u], bH + bo);
                    ldsm4t(bl[u], bL + bo);
                }
#pragma unroll
                for (int i = 0; i < 2; ++i)
#pragma unroll
                    for (int u = 0; u < 2; ++u)
#pragma unroll
                        for (int v = 0; v < 2; ++v) {
                            float* a4 = acc[i][u * 2 + v];
                            mma16816(a4, ah[i], bh[u][2 * v], bh[u][2 * v + 1]);
                            mma16816(a4, ah[i], bl[u][2 * v], bl[u][2 * v + 1]);
                            mma16816(a4, al[i], bh[u][2 * v], bh[u][2 * v + 1]);
                        }
            }

            // in-register score combine: out += s[p][m] * acc
#pragma unroll
            for (int i = 0; i < 2; ++i) {
                int pr = wp + i * 16 + (lane >> 2);
                float s0 = sS[pr * 8 + m];
                float s1 = sS[(pr + 8) * 8 + m];
#pragma unroll
                for (int j = 0; j < 4; ++j) {
                    out[i][j][0] = fmaf(s0, acc[i][j][0], out[i][j][0]);
                    out[i][j][1] = fmaf(s0, acc[i][j][1], out[i][j][1]);
                    out[i][j][2] = fmaf(s1, acc[i][j][2], out[i][j][2]);
                    out[i][j][3] = fmaf(s1, acc[i][j][3], out[i][j][3]);
                }
            }
        }
        __syncthreads();   // all warps done reading A before transpose overwrite

        // ---- epilogue: regs -> smem [64c][268p] (aliases A) -> coalesced STG ----
        float* tb = (float*)smem;
#pragma unroll
        for (int i = 0; i < 2; ++i) {
            int pr = wp + i * 16 + (lane >> 2);
#pragma unroll
            for (int j = 0; j < 4; ++j) {
                int c0 = wn + j * 8 + (lane & 3) * 2;
                tb[c0 * LDT + pr]           = out[i][j][0];
                tb[(c0 + 1) * LDT + pr]     = out[i][j][1];
                tb[c0 * LDT + pr + 8]       = out[i][j][2];
                tb[(c0 + 1) * LDT + pr + 8] = out[i][j][3];
            }
        }
        __syncthreads();

#pragma unroll
        for (int ii = 0; ii < 4; ++ii) {
            int cc = (wid << 2) + ii;
            float4 v1 = *(const float4*)(tb + cc * LDT + lane * 4);
            float4 v2 = *(const float4*)(tb + cc * LDT + 128 + lane * 4);
            float su = v1.x + v1.y + v1.z + v1.w + v2.x + v2.y + v2.z + v2.w;
            float sq = v1.x * v1.x + v1.y * v1.y + v1.z * v1.z + v1.w * v1.w
                     + v2.x * v2.x + v2.y * v2.y + v2.z * v2.z + v2.w * v2.w;
#pragma unroll
            for (int off = 16; off; off >>= 1) {
                su += __shfl_xor_sync(0xFFFFFFFFu, su, off);
                sq += __shfl_xor_sync(0xFFFFFFFFu, sq, off);
            }
            accsu[ii] += su;
            accsq[ii] += sq;
            float4* ob = (float4*)(outp + ((size_t)b * 64 + cc) * 131072 + n0 * 32);
            ob[lane] = v1;
            ob[lane + 32] = v2;
        }
    }

    // flush per-CTA BN stats
    if (lane == 0) {
#pragma unroll
        for (int ii = 0; ii < 4; ++ii) {
            int cc = (wid << 2) + ii;
            atomicAdd(&g_osum[cc], accsu[ii]);
            atomicAdd(&g_oss[cc], accsq[ii]);
        }
    }
}

// ---------------- K3: fold output BN (per-block) + apply BN + ReLU, 2x ILP ----------------
__global__ void k3_bnrelu(float* __restrict__ outp, const float* __restrict__ gout,
                          const float* __restrict__ bout) {
    __shared__ float ssc[64], sbi[64];
    if (threadIdx.x < 64) {
        int i = threadIdx.x;
        const float P = (float)NPTS;
        float mean = g_osum[i] / P;
        float var = g_oss[i] / P - mean * mean;
        float sc = rsqrtf(var + 1e-5f) * gout[i];
        ssc[i] = sc;
        sbi[i] = bout[i] - mean * sc;
    }
    __syncthreads();
    const int total4 = 8388608;
    int stride = gridDim.x * blockDim.x * 2;
    for (int idx = (blockIdx.x * blockDim.x + threadIdx.x) * 2; idx < total4; idx += stride) {
        int cch = (idx >> 15) & 63;       // pair never straddles a channel (even start)
        float sc = ssc[cch], bi = sbi[cch];
        float4 v = ((const float4*)outp)[idx];
        float4 w = ((const float4*)outp)[idx + 1];
        v.x = fmaxf(fmaf(v.x, sc, bi), 0.f);
        v.y = fmaxf(fmaf(v.y, sc, bi), 0.f);
        v.z = fmaxf(fmaf(v.z, sc, bi), 0.f);
        v.w = fmaxf(fmaf(v.w, sc, bi), 0.f);
        w.x = fmaxf(fmaf(w.x, sc, bi), 0.f);
        w.y = fmaxf(fmaf(w.y, sc, bi), 0.f);
        w.z = fmaxf(fmaf(w.z, sc, bi), 0.f);
        w.w = fmaxf(fmaf(w.w, sc, bi), 0.f);
        ((float4*)outp)[idx] = v;
        ((float4*)outp)[idx + 1] = w;
    }
}

extern "C" void kernel_launch(void* const* d_in, const int* in_sizes, int n_in,
                              void* d_out, int out_size) {
    const float* gxyz  = (const float*)d_in[0];
    const float* feat  = (const float*)d_in[1];
    const float* w1    = (const float*)d_in[2];
    const float* g1    = (const float*)d_in[3];
    const float* b1    = (const float*)d_in[4];
    const float* w2    = (const float*)d_in[5];
    const float* b2    = (const float*)d_in[6];
    const float* wbank = (const float*)d_in[7];
    const float* gout  = (const float*)d_in[8];
    const float* bout  = (const float*)d_in[9];
    float* outp = (float*)d_out;

    static int nsm = 0;
    if (nsm == 0) {
        cudaDeviceGetAttribute(&nsm, cudaDevAttrMultiProcessorCount, 0);
        if (nsm <= 0) nsm = 148;
    }

    cudaFuncSetAttribute(k2_mma, cudaFuncAttributeMaxDynamicSharedMemorySize, SMEM_SZ);

    k0_zero<<<1, 64>>>();
    k1_stats<<<128, 512>>>(gxyz, w1, wbank);
    k2_mma<<<nsm, 512, SMEM_SZ>>>(gxyz, feat, w1, w2, b2, g1, b1, outp);
    k3_bnrelu<<<2048, 512>>>(outp, gout, bout);
}